// round 6
// baseline (speedup 1.0000x reference)
#include <cuda_runtime.h>
#include <math.h>

#define TOK  4096
#define BB   2
#define SS   2048
#define D1   512
#define D2   1024
#define NH   8
#define HD   128
#define NBG  4
#define BLKG 256
#define KSZ  4
#define EPSF 1e-5f

// ---------------- scratch (device globals; no allocation allowed) -------------
static __device__ float g_xn[TOK*D1];
static __device__ float g_a [TOK*D2];
static __device__ float g_bg[TOK*D2];
static __device__ float g_qk[TOK*D2];
static __device__ float g_qh[TOK*D2];
static __device__ float g_kh[TOK*D2];
static __device__ float g_vh[TOK*D2];
static __device__ float g_Ho[TOK*D2];
static __device__ float g_h2[TOK*D2];
static __device__ float g_wc [KSZ*D2*D2];   // conv_w transposed [kc][j][o]
static __device__ float g_wc2[KSZ*D1*D2];   // folded W1@Wc_kc   [kc][i][o]
static __device__ float g_be [D2];          // full effective bias
static __device__ float g_bek[KSZ*D2];      // per-kc bias m1b@Wc_kc
static __device__ float g_Wq[D2*D2];
static __device__ float g_Wk[D2*D2];
static __device__ float g_Wv[D2*D2];
static __device__ float g_wie[D2*NH];
static __device__ float g_wfe[D2*NH];
static __device__ float g_it[BB*NH*SS];
static __device__ float g_ft[BB*NH*SS];
static __device__ float g_cs[BB*NH*SS];
static __device__ float g_mm[BB*NH*SS];
static __device__ float g_Mx[BB*NH*SS];
static __device__ float g_mtmax[BB*NH*32];

// ---------------- helpers ------------------------------------------------------
__device__ __forceinline__ void mma8(float* d, const unsigned* a, const unsigned* b){
    asm volatile("mma.sync.aligned.m16n8k8.row.col.f32.tf32.tf32.f32 "
        "{%0,%1,%2,%3}, {%4,%5,%6,%7}, {%8,%9}, {%0,%1,%2,%3};\n"
        : "+f"(d[0]), "+f"(d[1]), "+f"(d[2]), "+f"(d[3])
        : "r"(a[0]), "r"(a[1]), "r"(a[2]), "r"(a[3]), "r"(b[0]), "r"(b[1]));
}
__device__ __forceinline__ float silu_f(float x){ return x / (1.f + __expf(-x)); }
__device__ __forceinline__ unsigned smem_u32(const void* p){
    return (unsigned)__cvta_generic_to_shared(p);
}
__device__ __forceinline__ void cpa16(unsigned dst, const void* src, unsigned sz){
    asm volatile("cp.async.cg.shared.global [%0], [%1], 16, %2;\n"
                 :: "r"(dst), "l"(src), "r"(sz));
}
__device__ __forceinline__ void cpa_commit(){ asm volatile("cp.async.commit_group;\n" ::: "memory"); }
template<int N> __device__ __forceinline__ void cpa_wait(){
    asm volatile("cp.async.wait_group %0;\n" :: "n"(N) : "memory");
}

// ========== pipelined TF32 GEMM: 128x128 tile, 256 thr, 8 warps x (64x32) ======
// 3-stage cp.async, one __syncthreads per K-tile.
#define ASTR 20
#define BSTR 136
#define A_ST (128*ASTR)
#define B_ST (16*BSTR)
#define SM3 ((3*A_ST + 3*B_ST)*4)

// CONVM: A is virtual [TOK, 2048]: A_ext[t][kc*512+i] = xn[t+kc-3][i], zero-padded
template<bool CONVM>
__device__ __forceinline__ void cp_stage(
    float* As, float* Bs, const float* __restrict__ A, int lda,
    const float* __restrict__ B, int ldb, int m0, int n0, int kt, int tid)
{
    if (tid < 128) {
        const float* asrc;
        unsigned sz = 16;
        if (CONVM) {
            int kc = kt >> 5, kin = (kt & 31) << 4;
            int gm = m0 + tid;
            int grow = gm + kc - 3;
            if ((gm & (SS - 1)) + kc < 3) { sz = 0; grow = gm; }
            asrc = A + (size_t)grow * lda + kin;
        } else {
            asrc = A + (size_t)(m0 + tid) * lda + (kt << 4);
        }
        unsigned ad = smem_u32(As + tid * ASTR);
#pragma unroll
        for (int c = 0; c < 4; c++) cpa16(ad + c * 16, asrc + c * 4, sz);
    } else {
        int t2 = tid - 128;
        const float* bsrc = B + (size_t)((kt << 4) + (t2 >> 3)) * ldb + n0 + ((t2 & 7) << 4);
        unsigned bd = smem_u32(Bs + (t2 >> 3) * BSTR + ((t2 & 7) << 4));
#pragma unroll
        for (int c = 0; c < 4; c++) cpa16(bd + c * 16, bsrc + c * 4, 16);
    }
}

__device__ __forceinline__ void mm_stage(
    const float* As, const float* Bs, float acc[4][4][4],
    int wm, int wn, int grp, int qid)
{
#pragma unroll
    for (int kk = 0; kk < 16; kk += 8) {
        unsigned aF[4][4], bF[4][2];
#pragma unroll
        for (int mi = 0; mi < 4; mi++) {
            int m = wm + mi * 16 + grp;
            aF[mi][0] = __float_as_uint(As[m*ASTR + kk + qid]);
            aF[mi][1] = __float_as_uint(As[(m+8)*ASTR + kk + qid]);
            aF[mi][2] = __float_as_uint(As[m*ASTR + kk + qid + 4]);
            aF[mi][3] = __float_as_uint(As[(m+8)*ASTR + kk + qid + 4]);
        }
#pragma unroll
        for (int ni = 0; ni < 4; ni++) {
            int n = wn + ni * 8 + grp;
            bF[ni][0] = __float_as_uint(Bs[(kk+qid)*BSTR + n]);
            bF[ni][1] = __float_as_uint(Bs[(kk+qid+4)*BSTR + n]);
        }
#pragma unroll
        for (int mi = 0; mi < 4; mi++)
#pragma unroll
            for (int ni = 0; ni < 4; ni++)
                mma8(acc[mi][ni], aF[mi], bF[ni]);
    }
}

// act: 0 none, 1 silu, 2 +residual, 3 conv-silu (boundary bias fix)
template<bool CONVM>
__device__ __forceinline__ void tg3_body(
    const float* __restrict__ A, int lda,
    const float* __restrict__ B, int ldb,
    const float* __restrict__ bias,
    const float* __restrict__ res, int ldr,
    float* __restrict__ C, int ldc, int K, int act, int m0, int n0)
{
    extern __shared__ float smp[];
    float* Asm = smp;
    float* Bsm = smp + 3 * A_ST;
    const int tid = threadIdx.x, lane = tid & 31, warp = tid >> 5;
    const int grp = lane >> 2, qid = lane & 3;
    const int wm = (warp & 1) * 64, wn = (warp >> 1) * 32;
    const int nkt = K >> 4;

    float acc[4][4][4] = {};

    cp_stage<CONVM>(Asm, Bsm, A, lda, B, ldb, m0, n0, 0, tid); cpa_commit();
    cp_stage<CONVM>(Asm + A_ST, Bsm + B_ST, A, lda, B, ldb, m0, n0, 1, tid); cpa_commit();

    for (int kt = 0; kt < nkt; kt++) {
        cpa_wait<1>();
        __syncthreads();
        int nx = kt + 2;
        if (nx < nkt) {
            int s = nx % 3;
            cp_stage<CONVM>(Asm + s*A_ST, Bsm + s*B_ST, A, lda, B, ldb, m0, n0, nx, tid);
        }
        cpa_commit();
        int s = kt % 3;
        mm_stage(Asm + s*A_ST, Bsm + s*B_ST, acc, wm, wn, grp, qid);
    }

#pragma unroll
    for (int mi = 0; mi < 4; mi++) {
        int r0 = m0 + wm + mi * 16 + grp;
#pragma unroll
        for (int ni = 0; ni < 4; ni++) {
            int c = n0 + wn + ni * 8 + qid * 2;
            float b0 = 0.f, b1 = 0.f;
            if (bias) { b0 = bias[c]; b1 = bias[c+1]; }
            float v0 = acc[mi][ni][0] + b0, v1 = acc[mi][ni][1] + b1;
            float v2 = acc[mi][ni][2] + b0, v3 = acc[mi][ni][3] + b1;
            if (act == 3) {
                // first 3 tokens of each sequence: remove invalid-kc bias terms
                int sl = r0 & (SS - 1);
                if (sl < 3) {
                    for (int kc = 0; kc < 3 - sl; kc++) {
                        v0 -= g_bek[kc*D2 + c]; v1 -= g_bek[kc*D2 + c + 1];
                    }
                }
                v0 = silu_f(v0); v1 = silu_f(v1); v2 = silu_f(v2); v3 = silu_f(v3);
            }
            if (act == 1) { v0 = silu_f(v0); v1 = silu_f(v1); v2 = silu_f(v2); v3 = silu_f(v3); }
            if (act == 2) {
                v0 += res[(size_t)r0*ldr + c];     v1 += res[(size_t)r0*ldr + c + 1];
                v2 += res[(size_t)(r0+8)*ldr + c]; v3 += res[(size_t)(r0+8)*ldr + c + 1];
            }
            *(float2*)(C + (size_t)r0*ldc + c)     = make_float2(v0, v1);
            *(float2*)(C + (size_t)(r0+8)*ldc + c) = make_float2(v2, v3);
        }
    }
}

// ---------------- GEMM wrapper kernels ------------------------------------------
__global__ void __launch_bounds__(256, 2) mlp_k(
    const float* __restrict__ w1, const float* __restrict__ b1,
    const float* __restrict__ w2, const float* __restrict__ b2)
{
    if (blockIdx.z == 0)
        tg3_body<false>(g_xn, D1, w1, D2, b1, nullptr, 0, g_a,  D2, D1, 0,
                        blockIdx.y*128, blockIdx.x*128);
    else
        tg3_body<false>(g_xn, D1, w2, D2, b2, nullptr, 0, g_bg, D2, D1, 1,
                        blockIdx.y*128, blockIdx.x*128);
}

__global__ void __launch_bounds__(256, 2) conv_k()
{
    // K = 4*512 = 2048 virtual GEMM on xn with folded weights
    tg3_body<true>(g_xn, D1, g_wc2, D2, g_be, nullptr, 0, g_qk, D2, KSZ*D1, 3,
                   blockIdx.y*128, blockIdx.x*128);
}

__global__ void __launch_bounds__(256, 2) qkv_k(
    const float* __restrict__ qb, const float* __restrict__ kb, const float* __restrict__ vb)
{
    int z = blockIdx.z;
    const float* A    = (z == 2) ? g_a  : g_qk;
    const float* B    = (z == 0) ? g_Wq : (z == 1) ? g_Wk : g_Wv;
    const float* bias = (z == 0) ? qb   : (z == 1) ? kb   : vb;
    float*       C    = (z == 0) ? g_qh : (z == 1) ? g_kh : g_vh;
    tg3_body<false>(A, D2, B, D2, bias, nullptr, 0, C, D2, D2, 0,
                    blockIdx.y*128, blockIdx.x*128);
}

__global__ void __launch_bounds__(256, 2) fin_k(
    const float* __restrict__ fw, const float* __restrict__ fb,
    const float* __restrict__ x, float* __restrict__ out)
{
    tg3_body<false>(g_h2, D2, fw, D1, fb, x, D1, out, D1, D2, 2,
                    blockIdx.y*128, blockIdx.x*128);
}

// fold block-diagonal weights into dense projections (M=256 per group)
__global__ void __launch_bounds__(256, 2) foldw(
    const float* __restrict__ bq, const float* __restrict__ bk, const float* __restrict__ bv,
    const float* __restrict__ wq, const float* __restrict__ wk, const float* __restrict__ wv)
{
    int z = blockIdx.z;
    int mat = z >> 2, g = z & 3;
    const float* A = (mat == 0 ? bq : mat == 1 ? bk : bv) + (size_t)g*BLKG*BLKG;
    const float* B = (mat == 0 ? wq : mat == 1 ? wk : wv) + (size_t)g*BLKG*D2;
    float* C = (mat == 0 ? g_Wq : mat == 1 ? g_Wk : g_Wv) + (size_t)g*BLKG*D2;
    tg3_body<false>(A, BLKG, B, D2, nullptr, nullptr, 0, C, D2, BLKG, 0,
                    blockIdx.y*128, blockIdx.x*128);
}

// fold mlp1 into conv weights: Weff[kc] = W1 @ Wc_kc   [512,1024]
__global__ void __launch_bounds__(256, 2) weff_k(const float* __restrict__ w1)
{
    int kc = blockIdx.z;
    tg3_body<false>(w1, D2, g_wc + (size_t)kc*D2*D2, D2, nullptr, nullptr, 0,
                    g_wc2 + (size_t)kc*D1*D2, D2, D2, 0,
                    blockIdx.y*128, blockIdx.x*128);
}

// ---------------- small weight-prep kernels -------------------------------------
__global__ void conv_tr(const float* __restrict__ cw) {
    int idx = blockIdx.x * 256 + threadIdx.x;
    if (idx >= KSZ * D2 * D2) return;
    int o   = idx >> 12;
    int rem = idx & 4095;
    int i   = rem >> 2;
    int kk  = rem & 3;
    g_wc[((size_t)kk * D2 + i) * D2 + o] = cw[idx];
}

// per-kc bias m1b @ Wc_kc (atomic partial sums over j-chunks); g_bek pre-zeroed
__global__ void bek_k(const float* __restrict__ m1b) {
    int o  = blockIdx.x * 256 + threadIdx.x;   // gridDim.x = 4
    int kc = blockIdx.z;
    int j0 = blockIdx.y * 64;                  // gridDim.y = 16
    float s = 0.f;
    for (int j = j0; j < j0 + 64; j++)
        s += m1b[j] * g_wc[((size_t)kc*D2 + j)*D2 + o];
    atomicAdd(&g_bek[kc*D2 + o], s);
}
__global__ void bek_zero() {
    int i = blockIdx.x * 256 + threadIdx.x;
    if (i < KSZ*D2) g_bek[i] = 0.f;
}
__global__ void be_k(const float* __restrict__ cb) {
    int o = blockIdx.x * 256 + threadIdx.x;
    float s = cb[o];
#pragma unroll
    for (int kc = 0; kc < KSZ; kc++) s += g_bek[kc*D2 + o];
    g_be[o] = s;
}

__global__ void foldv(const float* __restrict__ bq, const float* __restrict__ bk,
                      const float* __restrict__ wi, const float* __restrict__ wf) {
    int idx = blockIdx.x * 256 + threadIdx.x;   // 8192
    int r = idx >> 3, h = idx & 7;
    int g = r >> 8, rl = r & 255;
    const float* aq = bq + ((size_t)g*BLKG + rl)*BLKG;
    const float* ak = bk + ((size_t)g*BLKG + rl)*BLKG;
    float si = 0.f, sf = 0.f;
    for (int o = 0; o < BLKG; o++) {
        si = fmaf(aq[o], wi[(g*BLKG + o)*NH + h], si);
        sf = fmaf(ak[o], wf[(g*BLKG + o)*NH + h], sf);
    }
    g_wie[r*NH + h] = si;
    g_wfe[r*NH + h] = sf;
}

// ---------------- layernorm over last dim (512), warp per token ---------------
__global__ void ln_kernel(const float* __restrict__ x,
                          const float* __restrict__ w,
                          const float* __restrict__ b) {
    int t = blockIdx.x * 8 + (threadIdx.x >> 5);
    int lane = threadIdx.x & 31;
    const float* xr = x + (size_t)t * D1;
    float v[16]; float s = 0.f;
#pragma unroll
    for (int i = 0; i < 16; i++) { v[i] = xr[lane + 32*i]; s += v[i]; }
#pragma unroll
    for (int o = 16; o; o >>= 1) s += __shfl_xor_sync(0xffffffffu, s, o);
    float mu = s * (1.f / D1);
    float q = 0.f;
#pragma unroll
    for (int i = 0; i < 16; i++) { float d = v[i] - mu; q += d * d; }
#pragma unroll
    for (int o = 16; o; o >>= 1) q += __shfl_xor_sync(0xffffffffu, q, o);
    float rstd = rsqrtf(q * (1.f / D1) + EPSF);
#pragma unroll
    for (int i = 0; i < 16; i++) {
        int c = lane + 32*i;
        g_xn[(size_t)t*D1 + c] = (v[i] - mu) * rstd * w[c] + b[c];
    }
}

// ---------------- gate pre-activations: warp per token, coalesced --------------
__global__ void gates2(const float* __restrict__ wib, const float* __restrict__ wfb) {
    int warp = threadIdx.x >> 5, lane = threadIdx.x & 31;
    int t = blockIdx.x * 8 + warp;
    const float* xr = g_qk + (size_t)t * D2;
    float si[8] = {}, sf[8] = {};
    for (int i = 0; i < 32; i++) {
        int idx = lane + 32*i;
        float xv = xr[idx];
        const float* wp = g_wie + idx*NH;
        const float* fp = g_wfe + idx*NH;
#pragma unroll
        for (int h = 0; h < 8; h++) {
            si[h] = fmaf(xv, wp[h], si[h]);
            sf[h] = fmaf(xv, fp[h], sf[h]);
        }
    }
#pragma unroll
    for (int h = 0; h < 8; h++) {
#pragma unroll
        for (int o = 16; o; o >>= 1) {
            si[h] += __shfl_xor_sync(0xffffffffu, si[h], o);
            sf[h] += __shfl_xor_sync(0xffffffffu, sf[h], o);
        }
    }
    if (lane == 0) {
        int b = t >> 11, s = t & (SS - 1);
#pragma unroll
        for (int h = 0; h < 8; h++) {
            g_it[((size_t)b*NH + h)*SS + s] = si[h] + wib[h];
            g_ft[((size_t)b*NH + h)*SS + s] = sf[h] + wfb[h];
        }
    }
}

// ---------------- per-(b,h) scans ----------------------------------------------
__global__ void scan_kernel() {
    int bh = blockIdx.x;
    int tid = threadIdx.x;
    int lane = tid & 31, w = tid >> 5;
    __shared__ float ws[8], wm[8];
    float carry_s = 0.f, carry_m = -1e30f;
    for (int c0 = 0; c0 < SS; c0 += 256) {
        int j = c0 + tid;
        float f = g_ft[(size_t)bh*SS + j];
        float ls = fminf(f, 0.f) - log1pf(expf(-fabsf(f)));
        float v = ls;
#pragma unroll
        for (int o = 1; o < 32; o <<= 1) {
            float u = __shfl_up_sync(0xffffffffu, v, o);
            if (lane >= o) v += u;
        }
        if (lane == 31) ws[w] = v;
        __syncthreads();
        if (tid == 0) { float run = 0.f; for (int i = 0; i < 8; i++) { run += ws[i]; ws[i] = run; } }
        __syncthreads();
        float cs = v + (w ? ws[w-1] : 0.f) + carry_s;
        g_cs[(size_t)bh*SS + j] = cs;
        float m = g_it[(size_t)bh*SS + j] - cs;
        g_mm[(size_t)bh*SS + j] = m;
        float mv = m;
#pragma unroll
        for (int o = 1; o < 32; o <<= 1) {
            float u = __shfl_up_sync(0xffffffffu, mv, o);
            if (lane >= o) mv = fmaxf(mv, u);
        }
        if (lane == 31) wm[w] = mv;
        __syncthreads();
        if (tid == 0) { float run = -1e30f; for (int i = 0; i < 8; i++) { run = fmaxf(run, wm[i]); wm[i] = run; } }
        __syncthreads();
        float Mpref = fmaxf(mv, w ? wm[w-1] : -1e30f);
        g_Mx[(size_t)bh*SS + j] = fmaxf(Mpref, carry_m);
        carry_s += ws[7];
        carry_m = fmaxf(carry_m, wm[7]);
        __syncthreads();
    }
}

__global__ void tilemax_kernel() {
    int bh = blockIdx.x;
    int t  = threadIdx.x;
    float mx = -1e30f;
    const float* mr = g_mm + (size_t)bh*SS + t*64;
    for (int i = 0; i < 64; i++) mx = fmaxf(mx, mr[i]);
    g_mtmax[bh*32 + t] = mx;
}

// ---------------- tensor-core mLSTM attention -----------------------------------
#define PADQ 132
#define PADK 132
#define PADV 136
#define PADP 72
#define ATTN_SMEM_FLOATS (64*PADQ + 64*PADV + 64*PADP + 64 + 128 + 64)

__global__ void __launch_bounds__(256) attn_tc() {
    extern __shared__ float sm[];
    float* Qs  = sm;
    float* KVs = Qs + 64*PADQ;
    float* Ps  = KVs + 64*PADV;
    float* mms = Ps + 64*PADP;
    float* red = mms + 64;
    float* inv = red + 128;

    int bh = blockIdx.y, b = bh >> 3, h = bh & 7;
    int qt = gridDim.x - 1 - blockIdx.x;
    int row0 = qt * 64;
    int tid = threadIdx.x, lane = tid & 31, warp = tid >> 5;
    int grp = lane >> 2, qid = lane & 3;
    int wm = (warp >> 1) * 16;
    int wn = (warp & 1) * 32;
    int wn2 = (warp & 1) * 64;
    int tok0 = b * SS + row0;

    for (int i = tid; i < 64*32; i += 256) {
        int r = i >> 5, d4 = (i & 31) * 4;
        *(float4*)&Qs[r*PADQ + d4] = *(const float4*)&g_qh[(size_t)(tok0+r)*D2 + h*HD + d4];
    }
    float Mi0 = g_Mx[(size_t)bh*SS + row0 + wm + grp];
    float Mi1 = g_Mx[(size_t)bh*SS + row0 + wm + grp + 8];
    float Mtop = g_Mx[(size_t)bh*SS + row0];

    float hacc[8][4] = {};
    float rs0 = 0.f, rs1 = 0.f;
    const float inv_tau = 0.03125f;

    for (int jt = 0; jt <= qt; jt++) {
        if (jt < qt && g_mtmax[bh*32 + jt] < Mtop - 35.f) continue;
        int jr0 = jt * 64;
        __syncthreads();
        for (int i = tid; i < 64*32; i += 256) {
            int r = i >> 5, d4 = (i & 31) * 4;
            *(float4*)&KVs[r*PADK + d4] = *(const float4*)&g_kh[(size_t)(b*SS+jr0+r)*D2 + h*HD + d4];
        }
        if (tid < 64) mms[tid] = g_mm[(size_t)bh*SS + jr0 + tid];
        __syncthreads();

        float sacc[4][4] = {};
#pragma unroll
        for (int d0 = 0; d0 < HD; d0 += 8) {
            unsigned aF[4];
            aF[0] = __float_as_uint(Qs[(wm+grp)*PADQ + d0 + qid]);
            aF[1] = __float_as_uint(Qs[(wm+grp+8)*PADQ + d0 + qid]);
            aF[2] = __float_as_uint(Qs[(wm+grp)*PADQ + d0 + qid + 4]);
            aF[3] = __float_as_uint(Qs[(wm+grp+8)*PADQ + d0 + qid + 4]);
#pragma unroll
            for (int ni = 0; ni < 4; ni++) {
                int jn = wn + ni*8 + grp;
                unsigned bF[2];
                bF[0] = __float_as_uint(KVs[jn*PADK + d0 + qid]);
                bF[1] = __float_as_uint(KVs[jn*PADK + d0 + qid + 4]);
                mma8(sacc[ni], aF, bF);
            }
        }
#pragma unroll
        for (int ni = 0; ni < 4; ni++) {
            int c0 = wn + ni*8 + 2*qid;
            int gj0 = jr0 + c0, gj1 = gj0 + 1;
            int gi0 = row0 + wm + grp, gi1 = gi0 + 8;
            float e0 = mms[c0], e1 = mms[c0+1];
            float p00 = (gj0 <= gi0) ? sacc[ni][0] * inv_tau * __expf(e0 - Mi0) : 0.f;
            float p01 = (gj1 <= gi0) ? sacc[ni][1] * inv_tau * __expf(e1 - Mi0) : 0.f;
            float p10 = (gj0 <= gi1) ? sacc[ni][2] * inv_tau * __expf(e0 - Mi1) : 0.f;
            float p11 = (gj1 <= gi1) ? sacc[ni][3] * inv_tau * __expf(e1 - Mi1) : 0.f;
            rs0 += p00 + p01; rs1 += p10 + p11;
            *(float2*)&Ps[(wm+grp)*PADP + c0]   = make_float2(p00, p01);
            *(float2*)&Ps[(wm+grp+8)*PADP + c0] = make_float2(p10, p11);
        }
        __syncthreads();
        for (int i = tid; i < 64*32; i += 256) {
            int r = i >> 5, d4 = (i & 31) * 4;
            *(float4*)&KVs[r*PADV + d4] = *(const float4*)&g_vh[(size_t)(b*SS+jr0+r)*D2 + h*HD + d4];
        }
        __syncthreads();
#pragma unroll
        for (int k0 = 0; k0 < 64; k0 += 8) {
            unsigned aF[4];
            aF[0] = __float_as_uint(Ps[(wm+grp)*PADP + k0 + qid]);
            aF[1] = __float_as_uint(Ps[(wm+grp+8)*PADP + k0 + qid]);
            aF[2] = __float_as_uint(Ps[(wm+grp)*PADP + k0 + qid + 4]);
            aF[3] = __float_as_uint(Ps[(wm+grp+8)*PADP + k0 + qid + 4]);
#pragma unroll
            for (int ni = 0; ni < 8; ni++) {
                int dn = wn2 + ni*8 + grp;
                unsigned bF[2];
                bF[0] = __float_as_uint(KVs[(k0+qid)*PADV + dn]);
                bF[1] = __float_as_uint(KVs[(k0+qid+4)*PADV + dn]);
                mma8(hacc[ni], aF, bF);
            }
        }
    }

    rs0 += __shfl_xor_sync(0xffffffffu, rs0, 1);
    rs0 += __shfl_xor_sync(0xffffffffu, rs0, 2);
    rs1 += __shfl_xor_sync(0xffffffffu, rs1, 1);
    rs1 += __shfl_xor_sync(0xffffffffu, rs1, 2);
    if (qid == 0) {
        red[(wm+grp)*2 + (warp & 1)]   = rs0;
        red[(wm+grp+8)*2 + (warp & 1)] = rs1;
    }
    __syncthreads();
    if (tid < 64) {
        float s2 = red[tid*2] + red[tid*2 + 1];
        int gi = row0 + tid;
        float floorv = __expf(-g_cs[(size_t)bh*SS + gi] - g_Mx[(size_t)bh*SS + gi]);
        inv[tid] = 1.f / (fmaxf(fabsf(s2), floorv) + 1e-8f);
    }
    __syncthreads();
    float iv0 = inv[wm + grp], iv1 = inv[wm + grp + 8];
#pragma unroll
    for (int ni = 0; ni < 8; ni++) {
        int dn = wn2 + ni*8 + 2*qid;
        size_t o0 = (size_t)(tok0 + wm + grp)*D2 + h*HD + dn;
        size_t o1 = (size_t)(tok0 + wm + grp + 8)*D2 + h*HD + dn;
        *(float2*)&g_Ho[o0] = make_float2(hacc[ni][0]*iv0, hacc[ni][1]*iv0);
        *(float2*)&g_Ho[o1] = make_float2(hacc[ni][2]*iv1, hacc[ni][3]*iv1);
    }
}

// ---------------- GroupNorm(heads) + skip*qk, then *bgate ---------------------
__global__ void gn_kernel(const float* __restrict__ gnw, const float* __restrict__ gnb,
                          const float* __restrict__ skip) {
    int g = blockIdx.x * 8 + (threadIdx.x >> 5);
    int lane = threadIdx.x & 31;
    int t = g >> 3, h = g & 7;
    const float* Hr = g_Ho + (size_t)t * D2 + h * HD;
    float4 v4 = *(const float4*)(Hr + lane * 4);
    float vv[4] = {v4.x, v4.y, v4.z, v4.w};
    float s = vv[0] + vv[1] + vv[2] + vv[3];
#pragma unroll
    for (int o = 16; o; o >>= 1) s += __shfl_xor_sync(0xffffffffu, s, o);
    float mu = s * (1.f / HD);
    float q = 0.f;
#pragma unroll
    for (int j = 0; j < 4; j++) { float d = vv[j] - mu; q += d * d; }
#pragma unroll
    for (int o = 16; o; o >>= 1) q += __shfl_xor_sync(0xffffffffu, q, o);
    float rstd = rsqrtf(q * (1.f / HD) + EPSF);
#pragma unroll
    for (int j = 0; j < 4; j++) {
        int c = h * HD + lane * 4 + j;
        float val = (vv[j] - mu) * rstd * gnw[c] + gnb[c];
        val += skip[c] * g_qk[(size_t)t * D2 + c];
        val *= g_bg[(size_t)t * D2 + c];
        g_h2[(size_t)t * D2 + c] = val;
    }
}

// ------------------------------- launcher --------------------------------------
extern "C" void kernel_launch(void* const* d_in, const int* in_sizes, int n_in,
                              void* d_out, int out_size) {
    (void)in_sizes; (void)n_in; (void)out_size;
    const float* x      = (const float*)d_in[0];
    const float* ln_w   = (const float*)d_in[1];
    const float* ln_b   = (const float*)d_in[2];
    const float* mlp1_w = (const float*)d_in[3];
    const float* mlp1_b = (const float*)d_in[4];
    const float* mlp2_w = (const float*)d_in[5];
    const float* mlp2_b = (const float*)d_in[6];
    const float* conv_w = (const float*)d_in[7];
    const float* conv_b = (const float*)d_in[8];
    const float* bq_w   = (const float*)d_in[9];
    const float* bk_w   = (const float*)d_in[10];
    const float* bv_w   = (const float*)d_in[11];
    const float* wq_b   = (const float*)d_in[13];
    const float* wq_w   = (const float*)d_in[12];
    const float* wk_w   = (const float*)d_in[14];
    const float* wk_b   = (const float*)d_in[15];
    const float* wv_w   = (const float*)d_in[16];
    const float* wv_b   = (const float*)d_in[17];
    const float* wi_w   = (const float*)d_in[18];
    const float* wi_b   = (const float*)d_in[19];
    const float* wf_w   = (const float*)d_in[20];
    const float* wf_b   = (const float*)d_in[21];
    const float* gn_w   = (const float*)d_in[22];
    const float* gn_b   = (const float*)d_in[23];
    const float* skip   = (const float*)d_in[24];
    const float* fin_w  = (const float*)d_in[25];
    const float* fin_b  = (const float*)d_in[26];

    // dynamic smem opt-in for pipelined GEMMs
    cudaFuncSetAttribute(mlp_k,  cudaFuncAttributeMaxDynamicSharedMemorySize, SM3);
    cudaFuncSetAttribute(qkv_k,  cudaFuncAttributeMaxDynamicSharedMemorySize, SM3);
    cudaFuncSetAttribute(conv_k, cudaFuncAttributeMaxDynamicSharedMemorySize, SM3);
    cudaFuncSetAttribute(fin_k,  cudaFuncAttributeMaxDynamicSharedMemorySize, SM3);
    cudaFuncSetAttribute(foldw,  cudaFuncAttributeMaxDynamicSharedMemorySize, SM3);
    cudaFuncSetAttribute(weff_k, cudaFuncAttributeMaxDynamicSharedMemorySize, SM3);

    // ---- weight preprocessing (activation-independent) ----
    conv_tr<<<(KSZ*D2*D2 + 255)/256, 256>>>(conv_w);
    foldw<<<dim3(8, 2, 12), 256, SM3>>>(bq_w, bk_w, bv_w, wq_w, wk_w, wv_w);
    foldv<<<32, 256>>>(bq_w, bk_w, wi_w, wf_w);
    weff_k<<<dim3(8, 4, 4), 256, SM3>>>(mlp1_w);
    bek_zero<<<(KSZ*D2 + 255)/256, 256>>>();
    bek_k<<<dim3(4, 16, KSZ), 256>>>(mlp1_b);
    be_k<<<4, 256>>>(conv_b);

    // ---- activations ----
    ln_kernel<<<TOK/8, 256>>>(x, ln_w, ln_b);
    mlp_k<<<dim3(D2/128, TOK/128, 2), 256, SM3>>>(mlp1_w, mlp1_b, mlp2_w, mlp2_b);
    conv_k<<<dim3(D2/128, TOK/128), 256, SM3>>>();

    gates2<<<TOK/8, 256>>>(wi_b, wf_b);
    scan_kernel<<<BB*NH, 256>>>();
    tilemax_kernel<<<BB*NH, 32>>>();

    qkv_k<<<dim3(D2/128, TOK/128, 3), 256, SM3>>>(wq_b, wk_b, wv_b);

    const int attn_smem = ATTN_SMEM_FLOATS * 4;
    cudaFuncSetAttribute(attn_tc, cudaFuncAttributeMaxDynamicSharedMemorySize, attn_smem);
    attn_tc<<<dim3(SS/64, BB*NH), 256, attn_smem>>>();

    gn_kernel<<<TOK*NH/8, 256>>>(gn_w, gn_b, skip);

    fin_k<<<dim3(D1/128, TOK/128), 256, SM3>>>(fin_w, fin_b, x, (float*)d_out);
}

// round 7
// speedup vs baseline: 1.2463x; 1.2463x over previous
#include <cuda_runtime.h>
#include <math.h>

#define TOK  4096
#define BB   2
#define SS   2048
#define D1   512
#define D2   1024
#define NH   8
#define HD   128
#define NBG  4
#define BLKG 256
#define KSZ  4
#define EPSF 1e-5f

// ---------------- scratch (device globals; no allocation allowed) -------------
static __device__ float g_xn[TOK*D1];
static __device__ float g_a [TOK*D2];
static __device__ float g_bg[TOK*D2];
static __device__ float g_qk[TOK*D2];
static __device__ float g_qh[TOK*D2];
static __device__ float g_kh[TOK*D2];
static __device__ float g_vh[TOK*D2];
static __device__ float g_Ho[TOK*D2];
static __device__ float g_h2[TOK*D2];
static __device__ float g_wc [KSZ*D2*D2];   // conv_w transposed [kc][j][o]
static __device__ float g_wc2[KSZ*D1*D2];   // folded W1@Wc_kc   [kc][i][o]
static __device__ float g_be [D2];          // full effective bias
static __device__ float g_bek[KSZ*D2];      // per-kc bias m1b@Wc_kc
static __device__ float g_Wq[D2*D2];
static __device__ float g_Wk[D2*D2];
static __device__ float g_Wv[D2*D2];
static __device__ float g_wie[D2*NH];
static __device__ float g_wfe[D2*NH];
static __device__ float g_it[BB*NH*SS];
static __device__ float g_ft[BB*NH*SS];
static __device__ float g_cs[BB*NH*SS];
static __device__ float g_mm[BB*NH*SS];
static __device__ float g_Mx[BB*NH*SS];
static __device__ float g_mtmax[BB*NH*32];

// ---------------- helpers ------------------------------------------------------
__device__ __forceinline__ void mma8(float* d, const unsigned* a, const unsigned* b){
    asm volatile("mma.sync.aligned.m16n8k8.row.col.f32.tf32.tf32.f32 "
        "{%0,%1,%2,%3}, {%4,%5,%6,%7}, {%8,%9}, {%0,%1,%2,%3};\n"
        : "+f"(d[0]), "+f"(d[1]), "+f"(d[2]), "+f"(d[3])
        : "r"(a[0]), "r"(a[1]), "r"(a[2]), "r"(a[3]), "r"(b[0]), "r"(b[1]));
}
__device__ __forceinline__ float silu_f(float x){ return x / (1.f + __expf(-x)); }

// ======== round-4 proven TF32 engine: 128x128 tile, 256 thr, 8 warps (64x32) ====
// register double-buffer global->smem, 2 syncs per 16-K tile.
// ACT: 0 none, 1 silu, 2 +residual, 3 conv-silu (boundary bias fix via g_bek)
template<int ACT>
__device__ __forceinline__ void tgemm_body(
    const float* __restrict__ A, int lda,
    const float* __restrict__ B, int ldb,
    const float* __restrict__ bias,
    const float* __restrict__ res, int ldr,
    float* __restrict__ C, int ldc, int K, int m0, int n0)
{
    __shared__ float As[2][16][136];
    __shared__ float Bs[2][16][136];
    const int tid = threadIdx.x;
    const int arow = tid >> 2, acol = (tid & 3) * 4;
    const int brow = tid >> 5, bcol = (tid & 31) * 4;
    const int lane = tid & 31, warp = tid >> 5;
    const int grp = lane >> 2, qid = lane & 3;
    const int wm = (warp & 1) * 64, wn = (warp >> 1) * 32;

    const float* Ap0 = A + (size_t)(m0 + arow) * lda + acol;
    const float* Ap1 = A + (size_t)(m0 + arow + 64) * lda + acol;
    const float* Bp0 = B + (size_t)brow * ldb + n0 + bcol;
    const float* Bp1 = B + (size_t)(brow + 8) * ldb + n0 + bcol;

    float acc[4][4][4] = {};
    const int nkt = K >> 4;

    {
        float4 a0 = *(const float4*)Ap0;
        float4 a1 = *(const float4*)Ap1;
        As[0][acol+0][arow] = a0.x; As[0][acol+1][arow] = a0.y;
        As[0][acol+2][arow] = a0.z; As[0][acol+3][arow] = a0.w;
        As[0][acol+0][arow+64] = a1.x; As[0][acol+1][arow+64] = a1.y;
        As[0][acol+2][arow+64] = a1.z; As[0][acol+3][arow+64] = a1.w;
        *(float4*)&Bs[0][brow][bcol]   = *(const float4*)Bp0;
        *(float4*)&Bs[0][brow+8][bcol] = *(const float4*)Bp1;
    }

    int cur = 0;
    for (int kt = 0; kt < nkt; kt++) {
        float4 na0, na1, nb0, nb1;
        if (kt + 1 < nkt) {
            na0 = *(const float4*)(Ap0 + (kt + 1) * 16);
            na1 = *(const float4*)(Ap1 + (kt + 1) * 16);
            nb0 = *(const float4*)(Bp0 + (size_t)(kt + 1) * 16 * ldb);
            nb1 = *(const float4*)(Bp1 + (size_t)(kt + 1) * 16 * ldb);
        }
        __syncthreads();
#pragma unroll
        for (int kk = 0; kk < 16; kk += 8) {
            unsigned aF[4][4], bF[4][2];
#pragma unroll
            for (int mi = 0; mi < 4; mi++) {
                int m = wm + mi * 16 + grp;
                aF[mi][0] = __float_as_uint(As[cur][kk+qid][m]);
                aF[mi][1] = __float_as_uint(As[cur][kk+qid][m+8]);
                aF[mi][2] = __float_as_uint(As[cur][kk+qid+4][m]);
                aF[mi][3] = __float_as_uint(As[cur][kk+qid+4][m+8]);
            }
#pragma unroll
            for (int ni = 0; ni < 4; ni++) {
                int n = wn + ni * 8 + grp;
                bF[ni][0] = __float_as_uint(Bs[cur][kk+qid][n]);
                bF[ni][1] = __float_as_uint(Bs[cur][kk+qid+4][n]);
            }
#pragma unroll
            for (int mi = 0; mi < 4; mi++)
#pragma unroll
                for (int ni = 0; ni < 4; ni++)
                    mma8(acc[mi][ni], aF[mi], bF[ni]);
        }
        if (kt + 1 < nkt) {
            int nxt = cur ^ 1;
            As[nxt][acol+0][arow] = na0.x; As[nxt][acol+1][arow] = na0.y;
            As[nxt][acol+2][arow] = na0.z; As[nxt][acol+3][arow] = na0.w;
            As[nxt][acol+0][arow+64] = na1.x; As[nxt][acol+1][arow+64] = na1.y;
            As[nxt][acol+2][arow+64] = na1.z; As[nxt][acol+3][arow+64] = na1.w;
            *(float4*)&Bs[nxt][brow][bcol]   = nb0;
            *(float4*)&Bs[nxt][brow+8][bcol] = nb1;
            cur = nxt;
        }
    }

#pragma unroll
    for (int mi = 0; mi < 4; mi++) {
        int r0 = m0 + wm + mi * 16 + grp;
#pragma unroll
        for (int ni = 0; ni < 4; ni++) {
            int c = n0 + wn + ni * 8 + qid * 2;
            float b0 = 0.f, b1 = 0.f;
            if (bias) { b0 = bias[c]; b1 = bias[c+1]; }
            float v0 = acc[mi][ni][0] + b0, v1 = acc[mi][ni][1] + b1;
            float v2 = acc[mi][ni][2] + b0, v3 = acc[mi][ni][3] + b1;
            if (ACT == 3) {
                int sl = r0 & (SS - 1);
                if (sl < 3) {
                    for (int kc = 0; kc < 3 - sl; kc++) {
                        v0 -= g_bek[kc*D2 + c]; v1 -= g_bek[kc*D2 + c + 1];
                    }
                }
                v0 = silu_f(v0); v1 = silu_f(v1); v2 = silu_f(v2); v3 = silu_f(v3);
            }
            if (ACT == 1) { v0 = silu_f(v0); v1 = silu_f(v1); v2 = silu_f(v2); v3 = silu_f(v3); }
            if (ACT == 2) {
                v0 += res[(size_t)r0*ldr + c];     v1 += res[(size_t)r0*ldr + c + 1];
                v2 += res[(size_t)(r0+8)*ldr + c]; v3 += res[(size_t)(r0+8)*ldr + c + 1];
            }
            *(float2*)(C + (size_t)r0*ldc + c)     = make_float2(v0, v1);
            *(float2*)(C + (size_t)(r0+8)*ldc + c) = make_float2(v2, v3);
        }
    }
}

// ---------------- GEMM wrapper kernels ------------------------------------------
__global__ void __launch_bounds__(256) mlp_k(
    const float* __restrict__ w1, const float* __restrict__ b1,
    const float* __restrict__ w2, const float* __restrict__ b2)
{
    if (blockIdx.z == 0)
        tgemm_body<0>(g_xn, D1, w1, D2, b1, nullptr, 0, g_a,  D2, D1,
                      blockIdx.y*128, blockIdx.x*128);
    else
        tgemm_body<1>(g_xn, D1, w2, D2, b2, nullptr, 0, g_bg, D2, D1,
                      blockIdx.y*128, blockIdx.x*128);
}

__global__ void __launch_bounds__(256) qkv_k(
    const float* __restrict__ qb, const float* __restrict__ kb, const float* __restrict__ vb)
{
    int z = blockIdx.z;
    const float* A    = (z == 2) ? g_a  : g_qk;
    const float* B    = (z == 0) ? g_Wq : (z == 1) ? g_Wk : g_Wv;
    const float* bias = (z == 0) ? qb   : (z == 1) ? kb   : vb;
    float*       C    = (z == 0) ? g_qh : (z == 1) ? g_kh : g_vh;
    tgemm_body<0>(A, D2, B, D2, bias, nullptr, 0, C, D2, D2,
                  blockIdx.y*128, blockIdx.x*128);
}

__global__ void __launch_bounds__(256) fin_k(
    const float* __restrict__ fw, const float* __restrict__ fb,
    const float* __restrict__ x, float* __restrict__ out)
{
    tgemm_body<2>(g_h2, D2, fw, D1, fb, x, D1, out, D1, D2,
                  blockIdx.y*128, blockIdx.x*128);
}

// fold block-diagonal weights into dense projections
__global__ void __launch_bounds__(256) foldw(
    const float* __restrict__ bq, const float* __restrict__ bk, const float* __restrict__ bv,
    const float* __restrict__ wq, const float* __restrict__ wk, const float* __restrict__ wv)
{
    int z = blockIdx.z;
    int mat = z >> 2, g = z & 3;
    const float* A = (mat == 0 ? bq : mat == 1 ? bk : bv) + (size_t)g*BLKG*BLKG;
    const float* B = (mat == 0 ? wq : mat == 1 ? wk : wv) + (size_t)g*BLKG*D2;
    float* C = (mat == 0 ? g_Wq : mat == 1 ? g_Wk : g_Wv) + (size_t)g*BLKG*D2;
    tgemm_body<0>(A, BLKG, B, D2, nullptr, nullptr, 0, C, D2, BLKG,
                  blockIdx.y * 128, blockIdx.x * 128);
}

// fold mlp1 into conv weights: Weff[kc] = W1 @ Wc_kc   [512,1024]
__global__ void __launch_bounds__(256) weff_k(const float* __restrict__ w1)
{
    int kc = blockIdx.z;
    tgemm_body<0>(w1, D2, g_wc + (size_t)kc*D2*D2, D2, nullptr, nullptr, 0,
                  g_wc2 + (size_t)kc*D1*D2, D2, D2,
                  blockIdx.y * 128, blockIdx.x * 128);
}

// ---------------- causal conv1d: K=2048 virtual GEMM on xn, folded weights ------
__global__ void __launch_bounds__(256) tconv2()
{
    __shared__ float As[2][16][136];
    __shared__ float Bs[2][16][136];
    const int tid = threadIdx.x;
    const int m0 = blockIdx.y * 128, n0 = blockIdx.x * 128;
    const int arow = tid >> 2, acol = (tid & 3) * 4;
    const int brow = tid >> 5, bcol = (tid & 31) * 4;
    const int lane = tid & 31, warp = tid >> 5;
    const int grp = lane >> 2, qid = lane & 3;
    const int wm = (warp & 1) * 64, wn = (warp >> 1) * 32;
    const int sl0 = (m0 + arow) & (SS - 1);

    float acc[4][4][4] = {};
    const int nkt = (KSZ * D1) >> 4;            // 128
    float4 zz = make_float4(0.f, 0.f, 0.f, 0.f);

#define CONV_LOAD(KT, A0, A1, B0, B1)                                                \
    {                                                                                \
        int kc  = (KT) >> 5;                                                         \
        int kin = ((KT) & 31) * 16;                                                  \
        bool ok0 = (sl0 + kc) >= 3;                                                  \
        const float* ar0 = g_xn + (size_t)(m0 + arow + kc - 3) * D1 + kin + acol;    \
        const float* ar1 = g_xn + (size_t)(m0 + arow + 64 + kc - 3) * D1 + kin + acol;\
        A0 = ok0 ? *(const float4*)ar0 : zz;                                         \
        A1 = *(const float4*)ar1;                                                    \
        const float* br = g_wc2 + (size_t)((kc << 9) + kin + brow) * D2 + n0 + bcol; \
        B0 = *(const float4*)br;                                                     \
        B1 = *(const float4*)(br + 8 * D2);                                          \
    }

#define SMEM_ST(BUF, A0, A1, B0, B1)                                                 \
    {                                                                                \
        As[BUF][acol+0][arow] = A0.x; As[BUF][acol+1][arow] = A0.y;                  \
        As[BUF][acol+2][arow] = A0.z; As[BUF][acol+3][arow] = A0.w;                  \
        As[BUF][acol+0][arow+64] = A1.x; As[BUF][acol+1][arow+64] = A1.y;            \
        As[BUF][acol+2][arow+64] = A1.z; As[BUF][acol+3][arow+64] = A1.w;            \
        *(float4*)&Bs[BUF][brow][bcol]   = B0;                                       \
        *(float4*)&Bs[BUF][brow+8][bcol] = B1;                                       \
    }

    {
        float4 a0, a1, b0, b1;
        CONV_LOAD(0, a0, a1, b0, b1);
        SMEM_ST(0, a0, a1, b0, b1);
    }
    int cur = 0;
    for (int kt = 0; kt < nkt; kt++) {
        float4 na0, na1, nb0, nb1;
        if (kt + 1 < nkt) CONV_LOAD(kt + 1, na0, na1, nb0, nb1);
        __syncthreads();
#pragma unroll
        for (int kk = 0; kk < 16; kk += 8) {
            unsigned aF[4][4], bF[4][2];
#pragma unroll
            for (int mi = 0; mi < 4; mi++) {
                int m = wm + mi * 16 + grp;
                aF[mi][0] = __float_as_uint(As[cur][kk+qid][m]);
                aF[mi][1] = __float_as_uint(As[cur][kk+qid][m+8]);
                aF[mi][2] = __float_as_uint(As[cur][kk+qid+4][m]);
                aF[mi][3] = __float_as_uint(As[cur][kk+qid+4][m+8]);
            }
#pragma unroll
            for (int ni = 0; ni < 4; ni++) {
                int n = wn + ni * 8 + grp;
                bF[ni][0] = __float_as_uint(Bs[cur][kk+qid][n]);
                bF[ni][1] = __float_as_uint(Bs[cur][kk+qid+4][n]);
            }
#pragma unroll
            for (int mi = 0; mi < 4; mi++)
#pragma unroll
                for (int ni = 0; ni < 4; ni++)
                    mma8(acc[mi][ni], aF[mi], bF[ni]);
        }
        if (kt + 1 < nkt) {
            int nxt = cur ^ 1;
            SMEM_ST(nxt, na0, na1, nb0, nb1);
            cur = nxt;
        }
    }

#pragma unroll
    for (int mi = 0; mi < 4; mi++) {
        int r0 = m0 + wm + mi * 16 + grp;
        int sl = r0 & (SS - 1);
#pragma unroll
        for (int ni = 0; ni < 4; ni++) {
            int c = n0 + wn + ni * 8 + qid * 2;
            float b0 = g_be[c], b1 = g_be[c+1];
            float v0 = acc[mi][ni][0] + b0, v1 = acc[mi][ni][1] + b1;
            float v2 = acc[mi][ni][2] + b0, v3 = acc[mi][ni][3] + b1;
            if (sl < 3) {
                for (int kc = 0; kc < 3 - sl; kc++) {
                    v0 -= g_bek[kc*D2 + c]; v1 -= g_bek[kc*D2 + c + 1];
                }
            }
            v0 = silu_f(v0); v1 = silu_f(v1); v2 = silu_f(v2); v3 = silu_f(v3);
            *(float2*)(g_qk + (size_t)r0*D2 + c)     = make_float2(v0, v1);
            *(float2*)(g_qk + (size_t)(r0+8)*D2 + c) = make_float2(v2, v3);
        }
    }
#undef CONV_LOAD
#undef SMEM_ST
}

// ---------------- small weight-prep kernels -------------------------------------
__global__ void conv_tr(const float* __restrict__ cw) {
    int idx = blockIdx.x * 256 + threadIdx.x;
    if (idx >= KSZ * D2 * D2) return;
    int o   = idx >> 12;
    int rem = idx & 4095;
    int i   = rem >> 2;
    int kk  = rem & 3;
    g_wc[((size_t)kk * D2 + i) * D2 + o] = cw[idx];
}

__global__ void bek_k(const float* __restrict__ m1b) {
    int o  = blockIdx.x * 256 + threadIdx.x;   // gridDim.x = 4
    int kc = blockIdx.z;
    int j0 = blockIdx.y * 64;                  // gridDim.y = 16
    float s = 0.f;
    for (int j = j0; j < j0 + 64; j++)
        s += m1b[j] * g_wc[((size_t)kc*D2 + j)*D2 + o];
    atomicAdd(&g_bek[kc*D2 + o], s);
}
__global__ void bek_zero() {
    int i = blockIdx.x * 256 + threadIdx.x;
    if (i < KSZ*D2) g_bek[i] = 0.f;
}
__global__ void be_k(const float* __restrict__ cb) {
    int o = blockIdx.x * 256 + threadIdx.x;
    float s = cb[o];
#pragma unroll
    for (int kc = 0; kc < KSZ; kc++) s += g_bek[kc*D2 + o];
    g_be[o] = s;
}

__global__ void foldv(const float* __restrict__ bq, const float* __restrict__ bk,
                      const float* __restrict__ wi, const float* __restrict__ wf) {
    int idx = blockIdx.x * 256 + threadIdx.x;   // 8192
    int r = idx >> 3, h = idx & 7;
    int g = r >> 8, rl = r & 255;
    const float* aq = bq + ((size_t)g*BLKG + rl)*BLKG;
    const float* ak = bk + ((size_t)g*BLKG + rl)*BLKG;
    float si = 0.f, sf = 0.f;
    for (int o = 0; o < BLKG; o++) {
        si = fmaf(aq[o], wi[(g*BLKG + o)*NH + h], si);
        sf = fmaf(ak[o], wf[(g*BLKG + o)*NH + h], sf);
    }
    g_wie[r*NH + h] = si;
    g_wfe[r*NH + h] = sf;
}

// ---------------- layernorm over last dim (512), warp per token ---------------
__global__ void ln_kernel(const float* __restrict__ x,
                          const float* __restrict__ w,
                          const float* __restrict__ b) {
    int t = blockIdx.x * 8 + (threadIdx.x >> 5);
    int lane = threadIdx.x & 31;
    const float* xr = x + (size_t)t * D1;
    float v[16]; float s = 0.f;
#pragma unroll
    for (int i = 0; i < 16; i++) { v[i] = xr[lane + 32*i]; s += v[i]; }
#pragma unroll
    for (int o = 16; o; o >>= 1) s += __shfl_xor_sync(0xffffffffu, s, o);
    float mu = s * (1.f / D1);
    float q = 0.f;
#pragma unroll
    for (int i = 0; i < 16; i++) { float d = v[i] - mu; q += d * d; }
#pragma unroll
    for (int o = 16; o; o >>= 1) q += __shfl_xor_sync(0xffffffffu, q, o);
    float rstd = rsqrtf(q * (1.f / D1) + EPSF);
#pragma unroll
    for (int i = 0; i < 16; i++) {
        int c = lane + 32*i;
        g_xn[(size_t)t*D1 + c] = (v[i] - mu) * rstd * w[c] + b[c];
    }
}

// ---------------- gate pre-activations: warp per token, coalesced --------------
__global__ void gates2(const float* __restrict__ wib, const float* __restrict__ wfb) {
    int warp = threadIdx.x >> 5, lane = threadIdx.x & 31;
    int t = blockIdx.x * 8 + warp;
    const float* xr = g_qk + (size_t)t * D2;
    float si[8] = {}, sf[8] = {};
    for (int i = 0; i < 32; i++) {
        int idx = lane + 32*i;
        float xv = xr[idx];
        const float* wp = g_wie + idx*NH;
        const float* fp = g_wfe + idx*NH;
#pragma unroll
        for (int h = 0; h < 8; h++) {
            si[h] = fmaf(xv, wp[h], si[h]);
            sf[h] = fmaf(xv, fp[h], sf[h]);
        }
    }
#pragma unroll
    for (int h = 0; h < 8; h++) {
#pragma unroll
        for (int o = 16; o; o >>= 1) {
            si[h] += __shfl_xor_sync(0xffffffffu, si[h], o);
            sf[h] += __shfl_xor_sync(0xffffffffu, sf[h], o);
        }
    }
    if (lane == 0) {
        int b = t >> 11, s = t & (SS - 1);
#pragma unroll
        for (int h = 0; h < 8; h++) {
            g_it[((size_t)b*NH + h)*SS + s] = si[h] + wib[h];
            g_ft[((size_t)b*NH + h)*SS + s] = sf[h] + wfb[h];
        }
    }
}

// ---------------- per-(b,h) scans ----------------------------------------------
__global__ void scan_kernel() {
    int bh = blockIdx.x;
    int tid = threadIdx.x;
    int lane = tid & 31, w = tid >> 5;
    __shared__ float ws[8], wm[8];
    float carry_s = 0.f, carry_m = -1e30f;
    for (int c0 = 0; c0 < SS; c0 += 256) {
        int j = c0 + tid;
        float f = g_ft[(size_t)bh*SS + j];
        float ls = fminf(f, 0.f) - log1pf(expf(-fabsf(f)));
        float v = ls;
#pragma unroll
        for (int o = 1; o < 32; o <<= 1) {
            float u = __shfl_up_sync(0xffffffffu, v, o);
            if (lane >= o) v += u;
        }
        if (lane == 31) ws[w] = v;
        __syncthreads();
        if (tid == 0) { float run = 0.f; for (int i = 0; i < 8; i++) { run += ws[i]; ws[i] = run; } }
        __syncthreads();
        float cs = v + (w ? ws[w-1] : 0.f) + carry_s;
        g_cs[(size_t)bh*SS + j] = cs;
        float m = g_it[(size_t)bh*SS + j] - cs;
        g_mm[(size_t)bh*SS + j] = m;
        float mv = m;
#pragma unroll
        for (int o = 1; o < 32; o <<= 1) {
            float u = __shfl_up_sync(0xffffffffu, mv, o);
            if (lane >= o) mv = fmaxf(mv, u);
        }
        if (lane == 31) wm[w] = mv;
        __syncthreads();
        if (tid == 0) { float run = -1e30f; for (int i = 0; i < 8; i++) { run = fmaxf(run, wm[i]); wm[i] = run; } }
        __syncthreads();
        float Mpref = fmaxf(mv, w ? wm[w-1] : -1e30f);
        g_Mx[(size_t)bh*SS + j] = fmaxf(Mpref, carry_m);
        carry_s += ws[7];
        carry_m = fmaxf(carry_m, wm[7]);
        __syncthreads();
    }
}

__global__ void tilemax_kernel() {
    int bh = blockIdx.x;
    int t  = threadIdx.x;
    float mx = -1e30f;
    const float* mr = g_mm + (size_t)bh*SS + t*64;
    for (int i = 0; i < 64; i++) mx = fmaxf(mx, mr[i]);
    g_mtmax[bh*32 + t] = mx;
}

// ---------------- tensor-core mLSTM attention -----------------------------------
#define PADQ 132
#define PADK 132
#define PADV 136
#define PADP 72
#define ATTN_SMEM_FLOATS (64*PADQ + 64*PADV + 64*PADP + 64 + 128 + 64)

__global__ void __launch_bounds__(256) attn_tc() {
    extern __shared__ float sm[];
    float* Qs  = sm;
    float* KVs = Qs + 64*PADQ;
    float* Ps  = KVs + 64*PADV;
    float* mms = Ps + 64*PADP;
    float* red = mms + 64;
    float* inv = red + 128;

    int bh = blockIdx.y, b = bh >> 3, h = bh & 7;
    int qt = gridDim.x - 1 - blockIdx.x;
    int row0 = qt * 64;
    int tid = threadIdx.x, lane = tid & 31, warp = tid >> 5;
    int grp = lane >> 2, qid = lane & 3;
    int wm = (warp >> 1) * 16;
    int wn = (warp & 1) * 32;
    int wn2 = (warp & 1) * 64;
    int tok0 = b * SS + row0;

    for (int i = tid; i < 64*32; i += 256) {
        int r = i >> 5, d4 = (i & 31) * 4;
        *(float4*)&Qs[r*PADQ + d4] = *(const float4*)&g_qh[(size_t)(tok0+r)*D2 + h*HD + d4];
    }
    float Mi0 = g_Mx[(size_t)bh*SS + row0 + wm + grp];
    float Mi1 = g_Mx[(size_t)bh*SS + row0 + wm + grp + 8];
    float Mtop = g_Mx[(size_t)bh*SS + row0];

    float hacc[8][4] = {};
    float rs0 = 0.f, rs1 = 0.f;
    const float inv_tau = 0.03125f;

    for (int jt = 0; jt <= qt; jt++) {
        if (jt < qt && g_mtmax[bh*32 + jt] < Mtop - 35.f) continue;
        int jr0 = jt * 64;
        __syncthreads();
        for (int i = tid; i < 64*32; i += 256) {
            int r = i >> 5, d4 = (i & 31) * 4;
            *(float4*)&KVs[r*PADK + d4] = *(const float4*)&g_kh[(size_t)(b*SS+jr0+r)*D2 + h*HD + d4];
        }
        if (tid < 64) mms[tid] = g_mm[(size_t)bh*SS + jr0 + tid];
        __syncthreads();

        float sacc[4][4] = {};
#pragma unroll
        for (int d0 = 0; d0 < HD; d0 += 8) {
            unsigned aF[4];
            aF[0] = __float_as_uint(Qs[(wm+grp)*PADQ + d0 + qid]);
            aF[1] = __float_as_uint(Qs[(wm+grp+8)*PADQ + d0 + qid]);
            aF[2] = __float_as_uint(Qs[(wm+grp)*PADQ + d0 + qid + 4]);
            aF[3] = __float_as_uint(Qs[(wm+grp+8)*PADQ + d0 + qid + 4]);
#pragma unroll
            for (int ni = 0; ni < 4; ni++) {
                int jn = wn + ni*8 + grp;
                unsigned bF[2];
                bF[0] = __float_as_uint(KVs[jn*PADK + d0 + qid]);
                bF[1] = __float_as_uint(KVs[jn*PADK + d0 + qid + 4]);
                mma8(sacc[ni], aF, bF);
            }
        }
#pragma unroll
        for (int ni = 0; ni < 4; ni++) {
            int c0 = wn + ni*8 + 2*qid;
            int gj0 = jr0 + c0, gj1 = gj0 + 1;
            int gi0 = row0 + wm + grp, gi1 = gi0 + 8;
            float e0 = mms[c0], e1 = mms[c0+1];
            float p00 = (gj0 <= gi0) ? sacc[ni][0] * inv_tau * __expf(e0 - Mi0) : 0.f;
            float p01 = (gj1 <= gi0) ? sacc[ni][1] * inv_tau * __expf(e1 - Mi0) : 0.f;
            float p10 = (gj0 <= gi1) ? sacc[ni][2] * inv_tau * __expf(e0 - Mi1) : 0.f;
            float p11 = (gj1 <= gi1) ? sacc[ni][3] * inv_tau * __expf(e1 - Mi1) : 0.f;
            rs0 += p00 + p01; rs1 += p10 + p11;
            *(float2*)&Ps[(wm+grp)*PADP + c0]   = make_float2(p00, p01);
            *(float2*)&Ps[(wm+grp+8)*PADP + c0] = make_float2(p10, p11);
        }
        __syncthreads();
        for (int i = tid; i < 64*32; i += 256) {
            int r = i >> 5, d4 = (i & 31) * 4;
            *(float4*)&KVs[r*PADV + d4] = *(const float4*)&g_vh[(size_t)(b*SS+jr0+r)*D2 + h*HD + d4];
        }
        __syncthreads();
#pragma unroll
        for (int k0 = 0; k0 < 64; k0 += 8) {
            unsigned aF[4];
            aF[0] = __float_as_uint(Ps[(wm+grp)*PADP + k0 + qid]);
            aF[1] = __float_as_uint(Ps[(wm+grp+8)*PADP + k0 + qid]);
            aF[2] = __float_as_uint(Ps[(wm+grp)*PADP + k0 + qid + 4]);
            aF[3] = __float_as_uint(Ps[(wm+grp+8)*PADP + k0 + qid + 4]);
#pragma unroll
            for (int ni = 0; ni < 8; ni++) {
                int dn = wn2 + ni*8 + grp;
                unsigned bF[2];
                bF[0] = __float_as_uint(KVs[(k0+qid)*PADV + dn]);
                bF[1] = __float_as_uint(KVs[(k0+qid+4)*PADV + dn]);
                mma8(hacc[ni], aF, bF);
            }
        }
    }

    rs0 += __shfl_xor_sync(0xffffffffu, rs0, 1);
    rs0 += __shfl_xor_sync(0xffffffffu, rs0, 2);
    rs1 += __shfl_xor_sync(0xffffffffu, rs1, 1);
    rs1 += __shfl_xor_sync(0xffffffffu, rs1, 2);
    if (qid == 0) {
        red[(wm+grp)*2 + (warp & 1)]   = rs0;
        red[(wm+grp+8)*2 + (warp & 1)] = rs1;
    }
    __syncthreads();
    if (tid < 64) {
        float s2 = red[tid*2] + red[tid*2 + 1];
        int gi = row0 + tid;
        float floorv = __expf(-g_cs[(size_t)bh*SS + gi] - g_Mx[(size_t)bh*SS + gi]);
        inv[tid] = 1.f / (fmaxf(fabsf(s2), floorv) + 1e-8f);
    }
    __syncthreads();
    float iv0 = inv[wm + grp], iv1 = inv[wm + grp + 8];
#pragma unroll
    for (int ni = 0; ni < 8; ni++) {
        int dn = wn2 + ni*8 + 2*qid;
        size_t o0 = (size_t)(tok0 + wm + grp)*D2 + h*HD + dn;
        size_t o1 = (size_t)(tok0 + wm + grp + 8)*D2 + h*HD + dn;
        *(float2*)&g_Ho[o0] = make_float2(hacc[ni][0]*iv0, hacc[ni][1]*iv0);
        *(float2*)&g_Ho[o1] = make_float2(hacc[ni][2]*iv1, hacc[ni][3]*iv1);
    }
}

// ---------------- GroupNorm(heads) + skip*qk, then *bgate ---------------------
__global__ void gn_kernel(const float* __restrict__ gnw, const float* __restrict__ gnb,
                          const float* __restrict__ skip) {
    int g = blockIdx.x * 8 + (threadIdx.x >> 5);
    int lane = threadIdx.x & 31;
    int t = g >> 3, h = g & 7;
    const float* Hr = g_Ho + (size_t)t * D2 + h * HD;
    float4 v4 = *(const float4*)(Hr + lane * 4);
    float vv[4] = {v4.x, v4.y, v4.z, v4.w};
    float s = vv[0] + vv[1] + vv[2] + vv[3];
#pragma unroll
    for (int o = 16; o; o >>= 1) s += __shfl_xor_sync(0xffffffffu, s, o);
    float mu = s * (1.f / HD);
    float q = 0.f;
#pragma unroll
    for (int j = 0; j < 4; j++) { float d = vv[j] - mu; q += d * d; }
#pragma unroll
    for (int o = 16; o; o >>= 1) q += __shfl_xor_sync(0xffffffffu, q, o);
    float rstd = rsqrtf(q * (1.f / HD) + EPSF);
#pragma unroll
    for (int j = 0; j < 4; j++) {
        int c = h * HD + lane * 4 + j;
        float val = (vv[j] - mu) * rstd * gnw[c] + gnb[c];
        val += skip[c] * g_qk[(size_t)t * D2 + c];
        val *= g_bg[(size_t)t * D2 + c];
        g_h2[(size_t)t * D2 + c] = val;
    }
}

// ------------------------------- launcher --------------------------------------
extern "C" void kernel_launch(void* const* d_in, const int* in_sizes, int n_in,
                              void* d_out, int out_size) {
    (void)in_sizes; (void)n_in; (void)out_size;
    const float* x      = (const float*)d_in[0];
    const float* ln_w   = (const float*)d_in[1];
    const float* ln_b   = (const float*)d_in[2];
    const float* mlp1_w = (const float*)d_in[3];
    const float* mlp1_b = (const float*)d_in[4];
    const float* mlp2_w = (const float*)d_in[5];
    const float* mlp2_b = (const float*)d_in[6];
    const float* conv_w = (const float*)d_in[7];
    const float* conv_b = (const float*)d_in[8];
    const float* bq_w   = (const float*)d_in[9];
    const float* bk_w   = (const float*)d_in[10];
    const float* bv_w   = (const float*)d_in[11];
    const float* wq_w   = (const float*)d_in[12];
    const float* wq_b   = (const float*)d_in[13];
    const float* wk_w   = (const float*)d_in[14];
    const float* wk_b   = (const float*)d_in[15];
    const float* wv_w   = (const float*)d_in[16];
    const float* wv_b   = (const float*)d_in[17];
    const float* wi_w   = (const float*)d_in[18];
    const float* wi_b   = (const float*)d_in[19];
    const float* wf_w   = (const float*)d_in[20];
    const float* wf_b   = (const float*)d_in[21];
    const float* gn_w   = (const float*)d_in[22];
    const float* gn_b   = (const float*)d_in[23];
    const float* skip   = (const float*)d_in[24];
    const float* fin_w  = (const float*)d_in[25];
    const float* fin_b  = (const float*)d_in[26];

    // ---- weight preprocessing (activation-independent) ----
    conv_tr<<<(KSZ*D2*D2 + 255)/256, 256>>>(conv_w);
    foldw<<<dim3(8, 2, 12), 256>>>(bq_w, bk_w, bv_w, wq_w, wk_w, wv_w);
    foldv<<<32, 256>>>(bq_w, bk_w, wi_w, wf_w);
    weff_k<<<dim3(8, 4, 4), 256>>>(mlp1_w);
    bek_zero<<<(KSZ*D2 + 255)/256, 256>>>();
    bek_k<<<dim3(4, 16, KSZ), 256>>>(mlp1_b);
    be_k<<<4, 256>>>(conv_b);

    // ---- activations ----
    ln_kernel<<<TOK/8, 256>>>(x, ln_w, ln_b);
    mlp_k<<<dim3(D2/128, TOK/128, 2), 256>>>(mlp1_w, mlp1_b, mlp2_w, mlp2_b);
    tconv2<<<dim3(D2/128, TOK/128), 256>>>();

    gates2<<<TOK/8, 256>>>(wi_b, wf_b);
    scan_kernel<<<BB*NH, 256>>>();
    tilemax_kernel<<<BB*NH, 32>>>();

    qkv_k<<<dim3(D2/128, TOK/128, 3), 256>>>(wq_b, wk_b, wv_b);

    const int attn_smem = ATTN_SMEM_FLOATS * 4;
    cudaFuncSetAttribute(attn_tc, cudaFuncAttributeMaxDynamicSharedMemorySize, attn_smem);
    attn_tc<<<dim3(SS/64, BB*NH), 256, attn_smem>>>();

    gn_kernel<<<TOK*NH/8, 256>>>(gn_w, gn_b, skip);

    fin_k<<<dim3(D1/128, TOK/128), 256>>>(fin_w, fin_b, x, (float*)d_out);
}